// round 9
// baseline (speedup 1.0000x reference)
// R7: R6 passing kernel + FMA-pipe exp2 (softmax off the MUFU pipe).
#include <cuda_runtime.h>
#include <cuda_bf16.h>
#include <cstdint>

// Problem constants
#define S_LEN 4096
#define HID   2048
#define NH    16
#define NKV   8
#define HD    128
#define QKV_W 4096   // 2048 q + 1024 k + 1024 v

// ---------------------------------------------------------------------------
// Scratch (allocation-free device globals)
// ---------------------------------------------------------------------------
__device__ float g_qkv[(size_t)S_LEN * QKV_W];   // fp32 QKV projection output

// split-bf16 operands for projection GEMMs
__device__ __nv_bfloat16 g_hs_hi[(size_t)S_LEN * HID];
__device__ __nv_bfloat16 g_hs_lo[(size_t)S_LEN * HID];
__device__ __nv_bfloat16 g_at_hi[(size_t)S_LEN * HID];   // attention out (split)
__device__ __nv_bfloat16 g_at_lo[(size_t)S_LEN * HID];
__device__ __nv_bfloat16 g_wqkv_hi[(size_t)QKV_W * HID];
__device__ __nv_bfloat16 g_wqkv_lo[(size_t)QKV_W * HID];
__device__ __nv_bfloat16 g_wo_hi[(size_t)HID * HID];
__device__ __nv_bfloat16 g_wo_lo[(size_t)HID * HID];

// split-bf16 Q/K/V for flash, [head][S][128]
__device__ __nv_bfloat16 g_q_hi[(size_t)NH  * S_LEN * HD];
__device__ __nv_bfloat16 g_q_lo[(size_t)NH  * S_LEN * HD];
__device__ __nv_bfloat16 g_k_hi[(size_t)NKV * S_LEN * HD];
__device__ __nv_bfloat16 g_k_lo[(size_t)NKV * S_LEN * HD];
__device__ __nv_bfloat16 g_v_hi[(size_t)NKV * S_LEN * HD];
__device__ __nv_bfloat16 g_v_lo[(size_t)NKV * S_LEN * HD];

// ---------------------------------------------------------------------------
// small PTX helpers
// ---------------------------------------------------------------------------
__device__ __forceinline__ void cp16(uint32_t dst, const void* src) {
    asm volatile("cp.async.cg.shared.global [%0], [%1], 16;\n" ::"r"(dst), "l"(src));
}
__device__ __forceinline__ void ldsm4(uint32_t* r, uint32_t addr) {
    asm volatile("ldmatrix.sync.aligned.m8n8.x4.shared.b16 {%0,%1,%2,%3}, [%4];\n"
                 : "=r"(r[0]), "=r"(r[1]), "=r"(r[2]), "=r"(r[3]) : "r"(addr));
}
__device__ __forceinline__ void ldsm4t(uint32_t* r, uint32_t addr) {
    asm volatile("ldmatrix.sync.aligned.m8n8.x4.trans.shared.b16 {%0,%1,%2,%3}, [%4];\n"
                 : "=r"(r[0]), "=r"(r[1]), "=r"(r[2]), "=r"(r[3]) : "r"(addr));
}
__device__ __forceinline__ void mma16816(float* c, const uint32_t* a, const uint32_t* b) {
    asm volatile(
        "mma.sync.aligned.m16n8k16.row.col.f32.bf16.bf16.f32 "
        "{%0,%1,%2,%3}, {%4,%5,%6,%7}, {%8,%9}, {%0,%1,%2,%3};\n"
        : "+f"(c[0]), "+f"(c[1]), "+f"(c[2]), "+f"(c[3])
        : "r"(a[0]), "r"(a[1]), "r"(a[2]), "r"(a[3]), "r"(b[0]), "r"(b[1]));
}
// Branch-free exp2 on the FMA/ALU pipes (no MUFU). Valid for x <= ~0 (softmax
// domain); masked scores (-1e30) clamp to -126 and yield ~2^-126 ~ 0.
__device__ __forceinline__ float fex2(float x) {
    x = fmaxf(x, -126.0f);
    const float zi = x + 12582912.0f;                  // round-to-nearest int
    const int   i  = __float_as_int(zi) - 0x4B400000;
    const float f  = x - (zi - 12582912.0f);           // f in [-0.5, 0.5]
    float p = 1.3333558e-3f;                           // Taylor 2^f, deg 5
    p = fmaf(p, f, 9.6181291e-3f);
    p = fmaf(p, f, 5.5504109e-2f);
    p = fmaf(p, f, 2.4022651e-1f);
    p = fmaf(p, f, 6.9314718e-1f);
    p = fmaf(p, f, 1.0f);
    return __int_as_float(__float_as_int(p) + (i << 23));
}
// pack (lo, hi) floats into bf16x2 (lo -> lower half)
__device__ __forceinline__ uint32_t pack2(float lo, float hi) {
    uint32_t r; asm("cvt.rn.bf16x2.f32 %0, %1, %2;" : "=r"(r) : "f"(hi), "f"(lo)); return r;
}
__device__ __forceinline__ float lo_f(uint32_t p) { return __uint_as_float(p << 16); }
__device__ __forceinline__ float hi_f(uint32_t p) { return __uint_as_float(p & 0xffff0000u); }

// ---------------------------------------------------------------------------
// fp32 -> (bf16 hi, bf16 lo)
// ---------------------------------------------------------------------------
__global__ __launch_bounds__(256) void cvt_split(const float* __restrict__ x,
                                                 __nv_bfloat16* __restrict__ hi,
                                                 __nv_bfloat16* __restrict__ lo,
                                                 int n)
{
    for (int i = blockIdx.x * blockDim.x + threadIdx.x; i < n;
         i += gridDim.x * blockDim.x) {
        float v = x[i];
        __nv_bfloat16 h = __float2bfloat16_rn(v);
        hi[i] = h;
        lo[i] = __float2bfloat16_rn(v - __bfloat162float(h));
    }
}

// ---------------------------------------------------------------------------
// Tensor-core split-bf16 GEMM: C = A @ B^T, fp32 out (validated R3/R6)
// ---------------------------------------------------------------------------
#define SSTR 40
#define ARR_B ((uint32_t)(128 * SSTR * 2))
#define STAGE_B (4u * ARR_B)

__global__ __launch_bounds__(256) void gemm_bf16x2(
    const __nv_bfloat16* __restrict__ Ah, const __nv_bfloat16* __restrict__ Al,
    const __nv_bfloat16* __restrict__ Bh, const __nv_bfloat16* __restrict__ Bl,
    float* __restrict__ C, int K, int ldc)
{
    extern __shared__ __nv_bfloat16 smg[];
    const int tid  = threadIdx.x;
    const int lane = tid & 31;
    const int wid  = tid >> 5;
    const int wm   = wid >> 1;
    const int wn   = wid & 1;
    const int mBase = blockIdx.y * 128;
    const int nBase = blockIdx.x * 128;
    const uint32_t smBase = (uint32_t)__cvta_generic_to_shared(smg);

    float c[2][8][4];
#pragma unroll
    for (int mi = 0; mi < 2; mi++)
#pragma unroll
        for (int ni = 0; ni < 8; ni++)
#pragma unroll
            for (int r = 0; r < 4; r++) c[mi][ni][r] = 0.f;

    const int r0 = tid >> 2, kc0 = (tid & 3) * 8;

    auto load_stage = [&](int s, int k0) {
#pragma unroll
        for (int half = 0; half < 2; half++) {
            const int row = r0 + half * 64;
            const size_t aoff = (size_t)(mBase + row) * K + k0 + kc0;
            const size_t boff = (size_t)(nBase + row) * K + k0 + kc0;
            const uint32_t d = smBase + s * STAGE_B + (uint32_t)(row * SSTR + kc0) * 2;
            cp16(d + 0 * ARR_B, Ah + aoff);
            cp16(d + 1 * ARR_B, Al + aoff);
            cp16(d + 2 * ARR_B, Bh + boff);
            cp16(d + 3 * ARR_B, Bl + boff);
        }
    };

    const int arow = wm * 32 + (lane & 15);
    const int akk  = (lane >> 4) * 8;
    const int brow = wn * 64 + ((lane >> 4) & 1) * 8 + (lane & 7);
    const int bkk  = ((lane >> 3) & 1) * 8;

    auto compute_stage = [&](int s) {
        const uint32_t base = smBase + s * STAGE_B;
#pragma unroll
        for (int ks = 0; ks < 32; ks += 16) {
            uint32_t ah[2][4], al[2][4];
#pragma unroll
            for (int mi = 0; mi < 2; mi++) {
                const uint32_t ad = base + (uint32_t)((arow + mi * 16) * SSTR + ks + akk) * 2;
                ldsm4(ah[mi], ad);
                ldsm4(al[mi], ad + ARR_B);
            }
#pragma unroll
            for (int bp = 0; bp < 4; bp++) {
                uint32_t bh[4], bl[4];
                const uint32_t bd = base + 2 * ARR_B +
                                    (uint32_t)((bp * 16 + brow) * SSTR + ks + bkk) * 2;
                ldsm4(bh, bd);
                ldsm4(bl, bd + ARR_B);
#pragma unroll
                for (int mi = 0; mi < 2; mi++) {
                    mma16816(c[mi][2 * bp + 0], ah[mi], bh + 0);
                    mma16816(c[mi][2 * bp + 1], ah[mi], bh + 2);
                    mma16816(c[mi][2 * bp + 0], al[mi], bh + 0);
                    mma16816(c[mi][2 * bp + 1], al[mi], bh + 2);
                    mma16816(c[mi][2 * bp + 0], ah[mi], bl + 0);
                    mma16816(c[mi][2 * bp + 1], ah[mi], bl + 2);
                }
            }
        }
    };

    const int nIter = K / 32;
    load_stage(0, 0);
    asm volatile("cp.async.commit_group;\n");

    for (int it = 0; it < nIter; it++) {
        const int s = it & 1;
        if (it + 1 < nIter) {
            load_stage(s ^ 1, (it + 1) * 32);
            asm volatile("cp.async.commit_group;\n");
            asm volatile("cp.async.wait_group 1;\n");
        } else {
            asm volatile("cp.async.wait_group 0;\n");
        }
        __syncthreads();
        compute_stage(s);
        __syncthreads();
    }

#pragma unroll
    for (int mi = 0; mi < 2; mi++) {
        const int row = mBase + wm * 32 + mi * 16 + (lane >> 2);
#pragma unroll
        for (int ni = 0; ni < 8; ni++) {
            const int col = nBase + wn * 64 + ni * 8 + (lane & 3) * 2;
            *(float2*)&C[(size_t)row * ldc + col] = make_float2(c[mi][ni][0], c[mi][ni][1]);
            *(float2*)&C[(size_t)(row + 8) * ldc + col] = make_float2(c[mi][ni][2], c[mi][ni][3]);
        }
    }
}
#define GEMM_SMEM (2 * STAGE_B)

// ---------------------------------------------------------------------------
// RMSNorm + RoPE + split to bf16 hi/lo, writing flash-friendly layouts.
// Q gets scale*log2e folded in (softmax uses exp2 domain).
// ---------------------------------------------------------------------------
#define QFOLD (0.08838834764831845f * 1.4426950408889634f)

__global__ __launch_bounds__(256) void norm_rope_split(const float* __restrict__ cosp,
                                                       const float* __restrict__ sinp,
                                                       const float* __restrict__ qw,
                                                       const float* __restrict__ kw)
{
    const int s = blockIdx.x;
    const int warp = threadIdx.x >> 5;
    const int lane = threadIdx.x & 31;

    const float* cs = cosp + (size_t)s * HD;
    const float* sn = sinp + (size_t)s * HD;

    for (int u = warp; u < 32; u += 8) {
        if (u < 24) {
            const float* x;
            const float* w;
            __nv_bfloat16 *oh, *ol;
            float fold;
            if (u < 16) {
                x = g_qkv + (size_t)s * QKV_W + u * HD;  w = qw;  fold = QFOLD;
                oh = g_q_hi + ((size_t)u * S_LEN + s) * HD;
                ol = g_q_lo + ((size_t)u * S_LEN + s) * HD;
            } else {
                x = g_qkv + (size_t)s * QKV_W + 2048 + (u - 16) * HD;  w = kw;  fold = 1.f;
                oh = g_k_hi + ((size_t)(u - 16) * S_LEN + s) * HD;
                ol = g_k_lo + ((size_t)(u - 16) * S_LEN + s) * HD;
            }
            float x0 = x[lane], x1 = x[lane + 32], x2 = x[lane + 64], x3 = x[lane + 96];
            float ss = x0*x0 + x1*x1 + x2*x2 + x3*x3;
#pragma unroll
            for (int m = 16; m >= 1; m >>= 1) ss += __shfl_xor_sync(0xffffffffu, ss, m);
            const float r = rsqrtf(ss * (1.0f / 128.0f) + 1e-6f);

            x0 = x0 * r * w[lane];      x1 = x1 * r * w[lane + 32];
            x2 = x2 * r * w[lane + 64]; x3 = x3 * r * w[lane + 96];

            const float c0 = cs[lane], c1 = cs[lane + 32], c2 = cs[lane + 64], c3 = cs[lane + 96];
            const float s0 = sn[lane], s1 = sn[lane + 32], s2 = sn[lane + 64], s3 = sn[lane + 96];

            float y0 = (x0 * c0 - x2 * s0) * fold;
            float y1 = (x1 * c1 - x3 * s1) * fold;
            float y2 = (x2 * c2 + x0 * s2) * fold;
            float y3 = (x3 * c3 + x1 * s3) * fold;

#pragma unroll
            for (int e = 0; e < 4; e++) {
                float v = (e == 0 ? y0 : e == 1 ? y1 : e == 2 ? y2 : y3);
                int i = lane + e * 32;
                __nv_bfloat16 h = __float2bfloat16_rn(v);
                oh[i] = h;
                ol[i] = __float2bfloat16_rn(v - __bfloat162float(h));
            }
        } else {
            const int kvh = u - 24;
            const float* x = g_qkv + (size_t)s * QKV_W + 3072 + kvh * HD;
            __nv_bfloat16* oh = g_v_hi + ((size_t)kvh * S_LEN + s) * HD;
            __nv_bfloat16* ol = g_v_lo + ((size_t)kvh * S_LEN + s) * HD;
#pragma unroll
            for (int e = 0; e < 4; e++) {
                int i = lane + e * 32;
                float v = x[i];
                __nv_bfloat16 h = __float2bfloat16_rn(v);
                oh[i] = h;
                ol[i] = __float2bfloat16_rn(v - __bfloat162float(h));
            }
        }
    }
}

// ---------------------------------------------------------------------------
// Tensor-core flash attention, split-bf16, causal, GQA.
// BQ=128, BK=64, 256 threads (8 warps x 16 rows). exp2-domain softmax on
// the FMA pipe (fex2), no MUFU.
// ---------------------------------------------------------------------------
#define FL_STR   136
#define FL_QH    0
#define FL_QL    (128 * FL_STR)
#define FL_ST0   (2 * 128 * FL_STR)
#define FL_ARR   (64 * FL_STR)
#define FL_STAGE (4 * FL_ARR)
#define FLASH_SMEM ((FL_ST0 + 2 * FL_STAGE) * 2)

__global__ __launch_bounds__(256, 1) void flash_mma()
{
    extern __shared__ __nv_bfloat16 sm[];
    const int h   = blockIdx.y;
    const int bx  = 31 - blockIdx.x;     // heavy tiles first
    const int qb  = bx * 128;
    const int kvh = h >> 1;
    const int tid  = threadIdx.x;
    const int lane = tid & 31;
    const int wid  = tid >> 5;
    const int wq0  = wid * 16;
    const uint32_t smB = (uint32_t)__cvta_generic_to_shared(sm);

    // ---- Q tile load (hi+lo) via cp.async ----
    {
        const __nv_bfloat16* qh = g_q_hi + ((size_t)h * S_LEN + qb) * HD;
        const __nv_bfloat16* ql = g_q_lo + ((size_t)h * S_LEN + qb) * HD;
#pragma unroll
        for (int t = 0; t < 8; t++) {
            int idx = tid + t * 256;              // 0..2047
            int row = idx >> 4, c = idx & 15;
            cp16(smB + (uint32_t)(FL_QH + row * FL_STR) * 2 + c * 16, qh + (size_t)row * HD + c * 8);
            cp16(smB + (uint32_t)(FL_QL + row * FL_STR) * 2 + c * 16, ql + (size_t)row * HD + c * 8);
        }
    }

    auto load_kv = [&](int s, int kt) {
        const size_t base = ((size_t)kvh * S_LEN + kt * 64) * HD;
        const __nv_bfloat16* srcs[4] = { g_k_hi + base, g_k_lo + base,
                                         g_v_hi + base, g_v_lo + base };
#pragma unroll
        for (int a = 0; a < 4; a++) {
            const uint32_t d0 = smB + (uint32_t)(FL_ST0 + s * FL_STAGE + a * FL_ARR) * 2;
#pragma unroll
            for (int t = 0; t < 4; t++) {
                int idx = tid + t * 256;          // 0..1023
                int row = idx >> 4, c = idx & 15;
                cp16(d0 + (uint32_t)(row * FL_STR) * 2 + c * 16, srcs[a] + (size_t)row * HD + c * 8);
            }
        }
    };

    float o[16][4];
#pragma unroll
    for (int nt = 0; nt < 16; nt++)
#pragma unroll
        for (int r = 0; r < 4; r++) o[nt][r] = 0.f;
    float mrow0 = -1e30f, mrow1 = -1e30f, lrow0 = 0.f, lrow1 = 0.f;

    const int arow = wq0 + (lane & 15);
    const int acol = (lane >> 4) * 8;
    const int brow = ((lane >> 4) & 1) * 8 + (lane & 7);
    const int bkk  = ((lane >> 3) & 1) * 8;
    const int vrow = (lane & 7) + ((lane >> 3) & 1) * 8;
    const int vcol = (lane >> 4) * 8;

    const int ktEnd = 2 * bx + 1;
    load_kv(0, 0);
    asm volatile("cp.async.commit_group;\n");

    for (int kt = 0; kt <= ktEnd; kt++) {
        const int s = kt & 1;
        if (kt < ktEnd) {
            load_kv(s ^ 1, kt + 1);
            asm volatile("cp.async.commit_group;\n");
            asm volatile("cp.async.wait_group 1;\n");
        } else {
            asm volatile("cp.async.wait_group 0;\n");
        }
        __syncthreads();

        const uint32_t khB = smB + (uint32_t)(FL_ST0 + s * FL_STAGE) * 2;
        const uint32_t vhB = khB + (uint32_t)(2 * FL_ARR) * 2;

        // ---- S = Q K^T (split, 3 passes) ----
        float sc[8][4];
#pragma unroll
        for (int nt = 0; nt < 8; nt++)
#pragma unroll
            for (int r = 0; r < 4; r++) sc[nt][r] = 0.f;

#pragma unroll
        for (int ks = 0; ks < 8; ks++) {
            uint32_t aqh[4], aql[4];
            const uint32_t aaddr = smB + (uint32_t)(arow * FL_STR + ks * 16 + acol) * 2;
            ldsm4(aqh, aaddr);
            ldsm4(aql, aaddr + (uint32_t)FL_QL * 2);
#pragma unroll
            for (int bn = 0; bn < 4; bn++) {
                uint32_t bh[4], bl[4];
                const uint32_t baddr = khB + (uint32_t)((bn * 16 + brow) * FL_STR + ks * 16 + bkk) * 2;
                ldsm4(bh, baddr);
                ldsm4(bl, baddr + (uint32_t)FL_ARR * 2);
                mma16816(sc[2 * bn + 0], aqh, bh + 0);
                mma16816(sc[2 * bn + 1], aqh, bh + 2);
                mma16816(sc[2 * bn + 0], aql, bh + 0);
                mma16816(sc[2 * bn + 1], aql, bh + 2);
                mma16816(sc[2 * bn + 0], aqh, bl + 0);
                mma16816(sc[2 * bn + 1], aqh, bl + 2);
            }
        }

        // ---- causal mask ----
        const int qi0 = qb + wq0 + (lane >> 2);
        if (kt >= 2 * bx) {
#pragma unroll
            for (int nt = 0; nt < 8; nt++) {
                const int c0 = kt * 64 + nt * 8 + (lane & 3) * 2;
                if (c0     > qi0)     sc[nt][0] = -1e30f;
                if (c0 + 1 > qi0)     sc[nt][1] = -1e30f;
                if (c0     > qi0 + 8) sc[nt][2] = -1e30f;
                if (c0 + 1 > qi0 + 8) sc[nt][3] = -1e30f;
            }
        }

        // ---- online softmax (exp2 domain, FMA-pipe exp) ----
        float mx0 = -1e30f, mx1 = -1e30f;
#pragma unroll
        for (int nt = 0; nt < 8; nt++) {
            mx0 = fmaxf(mx0, fmaxf(sc[nt][0], sc[nt][1]));
            mx1 = fmaxf(mx1, fmaxf(sc[nt][2], sc[nt][3]));
        }
        mx0 = fmaxf(mx0, __shfl_xor_sync(0xffffffffu, mx0, 1));
        mx0 = fmaxf(mx0, __shfl_xor_sync(0xffffffffu, mx0, 2));
        mx1 = fmaxf(mx1, __shfl_xor_sync(0xffffffffu, mx1, 1));
        mx1 = fmaxf(mx1, __shfl_xor_sync(0xffffffffu, mx1, 2));

        const float mn0 = fmaxf(mrow0, mx0);
        const float mn1 = fmaxf(mrow1, mx1);
        const float a0 = fex2(mrow0 - mn0);
        const float a1 = fex2(mrow1 - mn1);
        mrow0 = mn0; mrow1 = mn1;

#pragma unroll
        for (int nt = 0; nt < 16; nt++) {
            o[nt][0] *= a0; o[nt][1] *= a0;
            o[nt][2] *= a1; o[nt][3] *= a1;
        }

        float s0 = 0.f, s1 = 0.f;
#pragma unroll
        for (int nt = 0; nt < 8; nt++) {
            sc[nt][0] = fex2(sc[nt][0] - mn0);
            sc[nt][1] = fex2(sc[nt][1] - mn0);
            sc[nt][2] = fex2(sc[nt][2] - mn1);
            sc[nt][3] = fex2(sc[nt][3] - mn1);
            s0 += sc[nt][0] + sc[nt][1];
            s1 += sc[nt][2] + sc[nt][3];
        }
        s0 += __shfl_xor_sync(0xffffffffu, s0, 1);
        s0 += __shfl_xor_sync(0xffffffffu, s0, 2);
        s1 += __shfl_xor_sync(0xffffffffu, s1, 1);
        s1 += __shfl_xor_sync(0xffffffffu, s1, 2);
        lrow0 = lrow0 * a0 + s0;
        lrow1 = lrow1 * a1 + s1;

        // ---- O += P V (split, 3 passes; P packed from registers) ----
#pragma unroll
        for (int ks2 = 0; ks2 < 4; ks2++) {
            const int t0 = 2 * ks2, t1 = 2 * ks2 + 1;
            uint32_t ah[4], al[4];
            ah[0] = pack2(sc[t0][0], sc[t0][1]);
            ah[1] = pack2(sc[t0][2], sc[t0][3]);
            ah[2] = pack2(sc[t1][0], sc[t1][1]);
            ah[3] = pack2(sc[t1][2], sc[t1][3]);
            al[0] = pack2(sc[t0][0] - lo_f(ah[0]), sc[t0][1] - hi_f(ah[0]));
            al[1] = pack2(sc[t0][2] - lo_f(ah[1]), sc[t0][3] - hi_f(ah[1]));
            al[2] = pack2(sc[t1][0] - lo_f(ah[2]), sc[t1][1] - hi_f(ah[2]));
            al[3] = pack2(sc[t1][2] - lo_f(ah[3]), sc[t1][3] - hi_f(ah[3]));
#pragma unroll
            for (int dn = 0; dn < 8; dn++) {
                uint32_t bvh[4], bvl[4];
                const uint32_t vaddr = vhB +
                    (uint32_t)((ks2 * 16 + vrow) * FL_STR + dn * 16 + vcol) * 2;
                ldsm4t(bvh, vaddr);
                ldsm4t(bvl, vaddr + (uint32_t)FL_ARR * 2);
                mma16816(o[2 * dn + 0], ah, bvh + 0);
                mma16816(o[2 * dn + 1], ah, bvh + 2);
                mma16816(o[2 * dn + 0], al, bvh + 0);
                mma16816(o[2 * dn + 1], al, bvh + 2);
                mma16816(o[2 * dn + 0], ah, bvl + 0);
                mma16816(o[2 * dn + 1], ah, bvl + 2);
            }
        }
        __syncthreads();
    }

    // ---- epilogue: normalize, split to bf16 hi/lo, write g_at_* ----
    const float inv0 = 1.f / lrow0;
    const float inv1 = 1.f / lrow1;
    const int r0 = qb + wq0 + (lane >> 2);
    const int r1 = r0 + 8;
#pragma unroll
    for (int nt = 0; nt < 16; nt++) {
        const int col = h * HD + nt * 8 + (lane & 3) * 2;
        {
            float v0 = o[nt][0] * inv0, v1 = o[nt][1] * inv0;
            uint32_t ph = pack2(v0, v1);
            uint32_t pl = pack2(v0 - lo_f(ph), v1 - hi_f(ph));
            *(uint32_t*)(g_at_hi + (size_t)r0 * HID + col) = ph;
            *(uint32_t*)(g_at_lo + (size_t)r0 * HID + col) = pl;
        }
        {
            float v0 = o[nt][2] * inv1, v1 = o[nt][3] * inv1;
            uint32_t ph = pack2(v0, v1);
            uint32_t pl = pack2(v0 - lo_f(ph), v1 - hi_f(ph));
            *(uint32_t*)(g_at_hi + (size_t)r1 * HID + col) = ph;
            *(uint32_t*)(g_at_lo + (size_t)r1 * HID + col) = pl;
        }
    }
}

// ---------------------------------------------------------------------------
extern "C" void kernel_launch(void* const* d_in, const int* in_sizes, int n_in,
                              void* d_out, int out_size)
{
    const float* hs   = (const float*)d_in[0];
    const float* cosp = (const float*)d_in[1];
    const float* sinp = (const float*)d_in[2];
    const float* wq   = (const float*)d_in[3];
    const float* wk   = (const float*)d_in[4];
    const float* wv   = (const float*)d_in[5];
    const float* wo   = (const float*)d_in[6];
    const float* qw   = (const float*)d_in[7];
    const float* kw   = (const float*)d_in[8];
    float* out = (float*)d_out;

    float* qkv;
    cudaGetSymbolAddress((void**)&qkv, g_qkv);

    __nv_bfloat16 *hs_hi, *hs_lo, *at_hi, *at_lo, *wqkv_hi, *wqkv_lo, *wo_hi, *wo_lo;
    cudaGetSymbolAddress((void**)&hs_hi, g_hs_hi);
    cudaGetSymbolAddress((void**)&hs_lo, g_hs_lo);
    cudaGetSymbolAddress((void**)&at_hi, g_at_hi);
    cudaGetSymbolAddress((void**)&at_lo, g_at_lo);
    cudaGetSymbolAddress((void**)&wqkv_hi, g_wqkv_hi);
    cudaGetSymbolAddress((void**)&wqkv_lo, g_wqkv_lo);
    cudaGetSymbolAddress((void**)&wo_hi, g_wo_hi);
    cudaGetSymbolAddress((void**)&wo_lo, g_wo_lo);

    cudaFuncSetAttribute(gemm_bf16x2, cudaFuncAttributeMaxDynamicSharedMemorySize,
                         (int)GEMM_SMEM);
    cudaFuncSetAttribute(flash_mma, cudaFuncAttributeMaxDynamicSharedMemorySize,
                         (int)FLASH_SMEM);

    dim3 blk(256);

    // split conversions
    cvt_split<<<512, blk>>>(hs, hs_hi, hs_lo, S_LEN * HID);
    cvt_split<<<512, blk>>>(wq, wqkv_hi,                      wqkv_lo,                      2048 * HID);
    cvt_split<<<256, blk>>>(wk, wqkv_hi + (size_t)2048 * HID, wqkv_lo + (size_t)2048 * HID, 1024 * HID);
    cvt_split<<<256, blk>>>(wv, wqkv_hi + (size_t)3072 * HID, wqkv_lo + (size_t)3072 * HID, 1024 * HID);
    cvt_split<<<512, blk>>>(wo, wo_hi, wo_lo, HID * HID);

    // QKV projection
    gemm_bf16x2<<<dim3(QKV_W / 128, S_LEN / 128), blk, GEMM_SMEM>>>(
        hs_hi, hs_lo, wqkv_hi, wqkv_lo, qkv, HID, QKV_W);

    // norm + rope + split
    norm_rope_split<<<S_LEN, blk>>>(cosp, sinp, qw, kw);

    // flash attention (tensor cores) -> g_at_hi/lo
    flash_mma<<<dim3(S_LEN / 128, NH), blk, FLASH_SMEM>>>();

    // output projection
    gemm_bf16x2<<<dim3(HID / 128, S_LEN / 128), blk, GEMM_SMEM>>>(
        at_hi, at_lo, wo_hi, wo_lo, out, HID, HID);
}

// round 10
// speedup vs baseline: 1.0241x; 1.0241x over previous
// R10: ex2-revert + 3-stage GEMM pipeline + Q-in-registers flash + fast cvt.
#include <cuda_runtime.h>
#include <cuda_bf16.h>
#include <cstdint>

// Problem constants
#define S_LEN 4096
#define HID   2048
#define NH    16
#define NKV   8
#define HD    128
#define QKV_W 4096   // 2048 q + 1024 k + 1024 v

// ---------------------------------------------------------------------------
// Scratch (allocation-free device globals)
// ---------------------------------------------------------------------------
__device__ float g_qkv[(size_t)S_LEN * QKV_W];   // fp32 QKV projection output

// split-bf16 operands for projection GEMMs
__device__ __nv_bfloat16 g_hs_hi[(size_t)S_LEN * HID];
__device__ __nv_bfloat16 g_hs_lo[(size_t)S_LEN * HID];
__device__ __nv_bfloat16 g_at_hi[(size_t)S_LEN * HID];   // attention out (split)
__device__ __nv_bfloat16 g_at_lo[(size_t)S_LEN * HID];
__device__ __nv_bfloat16 g_wqkv_hi[(size_t)QKV_W * HID];
__device__ __nv_bfloat16 g_wqkv_lo[(size_t)QKV_W * HID];
__device__ __nv_bfloat16 g_wo_hi[(size_t)HID * HID];
__device__ __nv_bfloat16 g_wo_lo[(size_t)HID * HID];

// split-bf16 Q/K/V for flash, [head][S][128]
__device__ __nv_bfloat16 g_q_hi[(size_t)NH  * S_LEN * HD];
__device__ __nv_bfloat16 g_q_lo[(size_t)NH  * S_LEN * HD];
__device__ __nv_bfloat16 g_k_hi[(size_t)NKV * S_LEN * HD];
__device__ __nv_bfloat16 g_k_lo[(size_t)NKV * S_LEN * HD];
__device__ __nv_bfloat16 g_v_hi[(size_t)NKV * S_LEN * HD];
__device__ __nv_bfloat16 g_v_lo[(size_t)NKV * S_LEN * HD];

// ---------------------------------------------------------------------------
// small PTX helpers
// ---------------------------------------------------------------------------
__device__ __forceinline__ void cp16(uint32_t dst, const void* src) {
    asm volatile("cp.async.cg.shared.global [%0], [%1], 16;\n" ::"r"(dst), "l"(src));
}
__device__ __forceinline__ void ldsm4(uint32_t* r, uint32_t addr) {
    asm volatile("ldmatrix.sync.aligned.m8n8.x4.shared.b16 {%0,%1,%2,%3}, [%4];\n"
                 : "=r"(r[0]), "=r"(r[1]), "=r"(r[2]), "=r"(r[3]) : "r"(addr));
}
__device__ __forceinline__ void ldsm4t(uint32_t* r, uint32_t addr) {
    asm volatile("ldmatrix.sync.aligned.m8n8.x4.trans.shared.b16 {%0,%1,%2,%3}, [%4];\n"
                 : "=r"(r[0]), "=r"(r[1]), "=r"(r[2]), "=r"(r[3]) : "r"(addr));
}
__device__ __forceinline__ void mma16816(float* c, const uint32_t* a, const uint32_t* b) {
    asm volatile(
        "mma.sync.aligned.m16n8k16.row.col.f32.bf16.bf16.f32 "
        "{%0,%1,%2,%3}, {%4,%5,%6,%7}, {%8,%9}, {%0,%1,%2,%3};\n"
        : "+f"(c[0]), "+f"(c[1]), "+f"(c[2]), "+f"(c[3])
        : "r"(a[0]), "r"(a[1]), "r"(a[2]), "r"(a[3]), "r"(b[0]), "r"(b[1]));
}
__device__ __forceinline__ float ex2f(float x) {
    float y; asm("ex2.approx.ftz.f32 %0, %1;" : "=f"(y) : "f"(x)); return y;
}
// pack (lo, hi) floats into bf16x2 (lo -> lower half)
__device__ __forceinline__ uint32_t pack2(float lo, float hi) {
    uint32_t r; asm("cvt.rn.bf16x2.f32 %0, %1, %2;" : "=r"(r) : "f"(hi), "f"(lo)); return r;
}
__device__ __forceinline__ float lo_f(uint32_t p) { return __uint_as_float(p << 16); }
__device__ __forceinline__ float hi_f(uint32_t p) { return __uint_as_float(p & 0xffff0000u); }

// ---------------------------------------------------------------------------
// fp32 -> (bf16 hi, bf16 lo), vectorized (n4 = n/4 float4 chunks)
// ---------------------------------------------------------------------------
__global__ __launch_bounds__(256) void cvt_split(const float* __restrict__ x,
                                                 __nv_bfloat16* __restrict__ hi,
                                                 __nv_bfloat16* __restrict__ lo,
                                                 int n4)
{
    for (int i = blockIdx.x * blockDim.x + threadIdx.x; i < n4;
         i += gridDim.x * blockDim.x) {
        float4 v = ((const float4*)x)[i];
        uint32_t h0 = pack2(v.x, v.y);
        uint32_t h1 = pack2(v.z, v.w);
        uint32_t l0 = pack2(v.x - lo_f(h0), v.y - hi_f(h0));
        uint32_t l1 = pack2(v.z - lo_f(h1), v.w - hi_f(h1));
        ((uint2*)hi)[i] = make_uint2(h0, h1);
        ((uint2*)lo)[i] = make_uint2(l0, l1);
    }
}

// ---------------------------------------------------------------------------
// Tensor-core split-bf16 GEMM: C = A @ B^T, fp32 out.
// 3-stage cp.async pipeline, single __syncthreads per K-iter.
// ---------------------------------------------------------------------------
#define SSTR 40
#define ARR_B ((uint32_t)(128 * SSTR * 2))
#define STAGE_B (4u * ARR_B)
#define GEMM_SMEM (3 * STAGE_B)

__global__ __launch_bounds__(256, 1) void gemm_bf16x2(
    const __nv_bfloat16* __restrict__ Ah, const __nv_bfloat16* __restrict__ Al,
    const __nv_bfloat16* __restrict__ Bh, const __nv_bfloat16* __restrict__ Bl,
    float* __restrict__ C, int K, int ldc)
{
    extern __shared__ __nv_bfloat16 smg[];
    const int tid  = threadIdx.x;
    const int lane = tid & 31;
    const int wid  = tid >> 5;
    const int wm   = wid >> 1;
    const int wn   = wid & 1;
    const int mBase = blockIdx.y * 128;
    const int nBase = blockIdx.x * 128;
    const uint32_t smBase = (uint32_t)__cvta_generic_to_shared(smg);

    float c[2][8][4];
#pragma unroll
    for (int mi = 0; mi < 2; mi++)
#pragma unroll
        for (int ni = 0; ni < 8; ni++)
#pragma unroll
            for (int r = 0; r < 4; r++) c[mi][ni][r] = 0.f;

    const int r0 = tid >> 2, kc0 = (tid & 3) * 8;

    auto load_stage = [&](int s, int k0) {
#pragma unroll
        for (int half = 0; half < 2; half++) {
            const int row = r0 + half * 64;
            const size_t aoff = (size_t)(mBase + row) * K + k0 + kc0;
            const size_t boff = (size_t)(nBase + row) * K + k0 + kc0;
            const uint32_t d = smBase + s * STAGE_B + (uint32_t)(row * SSTR + kc0) * 2;
            cp16(d + 0 * ARR_B, Ah + aoff);
            cp16(d + 1 * ARR_B, Al + aoff);
            cp16(d + 2 * ARR_B, Bh + boff);
            cp16(d + 3 * ARR_B, Bl + boff);
        }
        asm volatile("cp.async.commit_group;\n");
    };

    const int arow = wm * 32 + (lane & 15);
    const int akk  = (lane >> 4) * 8;
    const int brow = wn * 64 + ((lane >> 4) & 1) * 8 + (lane & 7);
    const int bkk  = ((lane >> 3) & 1) * 8;

    auto compute_stage = [&](int s) {
        const uint32_t base = smBase + s * STAGE_B;
#pragma unroll
        for (int ks = 0; ks < 32; ks += 16) {
            uint32_t ah[2][4], al[2][4];
#pragma unroll
            for (int mi = 0; mi < 2; mi++) {
                const uint32_t ad = base + (uint32_t)((arow + mi * 16) * SSTR + ks + akk) * 2;
                ldsm4(ah[mi], ad);
                ldsm4(al[mi], ad + ARR_B);
            }
#pragma unroll
            for (int bp = 0; bp < 4; bp++) {
                uint32_t bh[4], bl[4];
                const uint32_t bd = base + 2 * ARR_B +
                                    (uint32_t)((bp * 16 + brow) * SSTR + ks + bkk) * 2;
                ldsm4(bh, bd);
                ldsm4(bl, bd + ARR_B);
#pragma unroll
                for (int mi = 0; mi < 2; mi++) {
                    mma16816(c[mi][2 * bp + 0], ah[mi], bh + 0);
                    mma16816(c[mi][2 * bp + 1], ah[mi], bh + 2);
                    mma16816(c[mi][2 * bp + 0], al[mi], bh + 0);
                    mma16816(c[mi][2 * bp + 1], al[mi], bh + 2);
                    mma16816(c[mi][2 * bp + 0], ah[mi], bl + 0);
                    mma16816(c[mi][2 * bp + 1], ah[mi], bl + 2);
                }
            }
        }
    };

    const int nIter = K / 32;       // >= 2 for K >= 64
    load_stage(0, 0);
    load_stage(1, 32);

    for (int it = 0; it < nIter; it++) {
        if (it + 1 < nIter) { asm volatile("cp.async.wait_group 1;\n"); }
        else                { asm volatile("cp.async.wait_group 0;\n"); }
        __syncthreads();
        if (it + 2 < nIter) load_stage((it + 2) % 3, (it + 2) * 32);
        compute_stage(it % 3);
    }

#pragma unroll
    for (int mi = 0; mi < 2; mi++) {
        const int row = mBase + wm * 32 + mi * 16 + (lane >> 2);
#pragma unroll
        for (int ni = 0; ni < 8; ni++) {
            const int col = nBase + wn * 64 + ni * 8 + (lane & 3) * 2;
            *(float2*)&C[(size_t)row * ldc + col] = make_float2(c[mi][ni][0], c[mi][ni][1]);
            *(float2*)&C[(size_t)(row + 8) * ldc + col] = make_float2(c[mi][ni][2], c[mi][ni][3]);
        }
    }
}

// ---------------------------------------------------------------------------
// RMSNorm + RoPE + split to bf16 hi/lo, writing flash-friendly layouts.
// Q gets scale*log2e folded in (softmax uses exp2 domain).
// ---------------------------------------------------------------------------
#define QFOLD (0.08838834764831845f * 1.4426950408889634f)

__global__ __launch_bounds__(256) void norm_rope_split(const float* __restrict__ cosp,
                                                       const float* __restrict__ sinp,
                                                       const float* __restrict__ qw,
                                                       const float* __restrict__ kw)
{
    const int s = blockIdx.x;
    const int warp = threadIdx.x >> 5;
    const int lane = threadIdx.x & 31;

    const float* cs = cosp + (size_t)s * HD;
    const float* sn = sinp + (size_t)s * HD;

    for (int u = warp; u < 32; u += 8) {
        if (u < 24) {
            const float* x;
            const float* w;
            __nv_bfloat16 *oh, *ol;
            float fold;
            if (u < 16) {
                x = g_qkv + (size_t)s * QKV_W + u * HD;  w = qw;  fold = QFOLD;
                oh = g_q_hi + ((size_t)u * S_LEN + s) * HD;
                ol = g_q_lo + ((size_t)u * S_LEN + s) * HD;
            } else {
                x = g_qkv + (size_t)s * QKV_W + 2048 + (u - 16) * HD;  w = kw;  fold = 1.f;
                oh = g_k_hi + ((size_t)(u - 16) * S_LEN + s) * HD;
                ol = g_k_lo + ((size_t)(u - 16) * S_LEN + s) * HD;
            }
            float x0 = x[lane], x1 = x[lane + 32], x2 = x[lane + 64], x3 = x[lane + 96];
            float ss = x0*x0 + x1*x1 + x2*x2 + x3*x3;
#pragma unroll
            for (int m = 16; m >= 1; m >>= 1) ss += __shfl_xor_sync(0xffffffffu, ss, m);
            const float r = rsqrtf(ss * (1.0f / 128.0f) + 1e-6f);

            x0 = x0 * r * w[lane];      x1 = x1 * r * w[lane + 32];
            x2 = x2 * r * w[lane + 64]; x3 = x3 * r * w[lane + 96];

            const float c0 = cs[lane], c1 = cs[lane + 32], c2 = cs[lane + 64], c3 = cs[lane + 96];
            const float s0 = sn[lane], s1 = sn[lane + 32], s2 = sn[lane + 64], s3 = sn[lane + 96];

            float y0 = (x0 * c0 - x2 * s0) * fold;
            float y1 = (x1 * c1 - x3 * s1) * fold;
            float y2 = (x2 * c2 + x0 * s2) * fold;
            float y3 = (x3 * c3 + x1 * s3) * fold;

#pragma unroll
            for (int e = 0; e < 4; e++) {
                float v = (e == 0 ? y0 : e == 1 ? y1 : e == 2 ? y2 : y3);
                int i = lane + e * 32;
                __nv_bfloat16 h = __float2bfloat16_rn(v);
                oh[i] = h;
                ol[i] = __float2bfloat16_rn(v - __bfloat162float(h));
            }
        } else {
            const int kvh = u - 24;
            const float* x = g_qkv + (size_t)s * QKV_W + 3072 + kvh * HD;
            __nv_bfloat16* oh = g_v_hi + ((size_t)kvh * S_LEN + s) * HD;
            __nv_bfloat16* ol = g_v_lo + ((size_t)kvh * S_LEN + s) * HD;
#pragma unroll
            for (int e = 0; e < 4; e++) {
                int i = lane + e * 32;
                float v = x[i];
                __nv_bfloat16 h = __float2bfloat16_rn(v);
                oh[i] = h;
                ol[i] = __float2bfloat16_rn(v - __bfloat162float(h));
            }
        }
    }
}

// ---------------------------------------------------------------------------
// Tensor-core flash attention, split-bf16, causal, GQA.
// BQ=128, BK=64, 256 threads (8 warps x 16 rows). Q fragments held in
// registers across the whole KV loop; exp2-domain softmax (MUFU ex2).
// ---------------------------------------------------------------------------
#define FL_STR   136
#define FL_QH    0
#define FL_QL    (128 * FL_STR)
#define FL_ST0   (2 * 128 * FL_STR)
#define FL_ARR   (64 * FL_STR)
#define FL_STAGE (4 * FL_ARR)
#define FLASH_SMEM ((FL_ST0 + 2 * FL_STAGE) * 2)

__global__ __launch_bounds__(256, 1) void flash_mma()
{
    extern __shared__ __nv_bfloat16 sm[];
    const int h   = blockIdx.y;
    const int bx  = 31 - blockIdx.x;     // heavy tiles first
    const int qb  = bx * 128;
    const int kvh = h >> 1;
    const int tid  = threadIdx.x;
    const int lane = tid & 31;
    const int wid  = tid >> 5;
    const int wq0  = wid * 16;
    const uint32_t smB = (uint32_t)__cvta_generic_to_shared(sm);

    const int arow = wq0 + (lane & 15);
    const int acol = (lane >> 4) * 8;
    const int brow = ((lane >> 4) & 1) * 8 + (lane & 7);
    const int bkk  = ((lane >> 3) & 1) * 8;
    const int vrow = (lane & 7) + ((lane >> 3) & 1) * 8;
    const int vcol = (lane >> 4) * 8;

    // ---- Q tile + KV0 via cp.async (one group) ----
    {
        const __nv_bfloat16* qh = g_q_hi + ((size_t)h * S_LEN + qb) * HD;
        const __nv_bfloat16* ql = g_q_lo + ((size_t)h * S_LEN + qb) * HD;
#pragma unroll
        for (int t = 0; t < 8; t++) {
            int idx = tid + t * 256;              // 0..2047
            int row = idx >> 4, c = idx & 15;
            cp16(smB + (uint32_t)(FL_QH + row * FL_STR) * 2 + c * 16, qh + (size_t)row * HD + c * 8);
            cp16(smB + (uint32_t)(FL_QL + row * FL_STR) * 2 + c * 16, ql + (size_t)row * HD + c * 8);
        }
    }

    auto load_kv = [&](int s, int kt) {
        const size_t base = ((size_t)kvh * S_LEN + kt * 64) * HD;
        const __nv_bfloat16* srcs[4] = { g_k_hi + base, g_k_lo + base,
                                         g_v_hi + base, g_v_lo + base };
#pragma unroll
        for (int a = 0; a < 4; a++) {
            const uint32_t d0 = smB + (uint32_t)(FL_ST0 + s * FL_STAGE + a * FL_ARR) * 2;
#pragma unroll
            for (int t = 0; t < 4; t++) {
                int idx = tid + t * 256;          // 0..1023
                int row = idx >> 4, c = idx & 15;
                cp16(d0 + (uint32_t)(row * FL_STR) * 2 + c * 16, srcs[a] + (size_t)row * HD + c * 8);
            }
        }
        asm volatile("cp.async.commit_group;\n");
    };

    load_kv(0, 0);                            // group 0 = Q + KV0
    asm volatile("cp.async.wait_group 0;\n");
    __syncthreads();

    // ---- Q fragments -> registers (reused every kt iteration) ----
    uint32_t qfh[8][4], qfl[8][4];
#pragma unroll
    for (int ks = 0; ks < 8; ks++) {
        const uint32_t aaddr = smB + (uint32_t)(arow * FL_STR + ks * 16 + acol) * 2;
        ldsm4(qfh[ks], aaddr);
        ldsm4(qfl[ks], aaddr + (uint32_t)FL_QL * 2);
    }

    float o[16][4];
#pragma unroll
    for (int nt = 0; nt < 16; nt++)
#pragma unroll
        for (int r = 0; r < 4; r++) o[nt][r] = 0.f;
    float mrow0 = -1e30f, mrow1 = -1e30f, lrow0 = 0.f, lrow1 = 0.f;

    const int ktEnd = 2 * bx + 1;

    for (int kt = 0; kt <= ktEnd; kt++) {
        const int s = kt & 1;
        if (kt < ktEnd) load_kv(s ^ 1, kt + 1);
        if (kt > 0) {
            if (kt < ktEnd) { asm volatile("cp.async.wait_group 1;\n"); }
            else            { asm volatile("cp.async.wait_group 0;\n"); }
            __syncthreads();
        }
        // kt == 0: slot 0 already loaded + synced in prologue

        const uint32_t khB = smB + (uint32_t)(FL_ST0 + s * FL_STAGE) * 2;
        const uint32_t vhB = khB + (uint32_t)(2 * FL_ARR) * 2;

        // ---- S = Q K^T (split, 3 passes; Q from registers) ----
        float sc[8][4];
#pragma unroll
        for (int nt = 0; nt < 8; nt++)
#pragma unroll
            for (int r = 0; r < 4; r++) sc[nt][r] = 0.f;

#pragma unroll
        for (int ks = 0; ks < 8; ks++) {
#pragma unroll
            for (int bn = 0; bn < 4; bn++) {
                uint32_t bh[4], bl[4];
                const uint32_t baddr = khB + (uint32_t)((bn * 16 + brow) * FL_STR + ks * 16 + bkk) * 2;
                ldsm4(bh, baddr);
                ldsm4(bl, baddr + (uint32_t)FL_ARR * 2);
                mma16816(sc[2 * bn + 0], qfh[ks], bh + 0);
                mma16816(sc[2 * bn + 1], qfh[ks], bh + 2);
                mma16816(sc[2 * bn + 0], qfl[ks], bh + 0);
                mma16816(sc[2 * bn + 1], qfl[ks], bh + 2);
                mma16816(sc[2 * bn + 0], qfh[ks], bl + 0);
                mma16816(sc[2 * bn + 1], qfh[ks], bl + 2);
            }
        }

        // ---- causal mask ----
        const int qi0 = qb + wq0 + (lane >> 2);
        if (kt >= 2 * bx) {
#pragma unroll
            for (int nt = 0; nt < 8; nt++) {
                const int c0 = kt * 64 + nt * 8 + (lane & 3) * 2;
                if (c0     > qi0)     sc[nt][0] = -1e30f;
                if (c0 + 1 > qi0)     sc[nt][1] = -1e30f;
                if (c0     > qi0 + 8) sc[nt][2] = -1e30f;
                if (c0 + 1 > qi0 + 8) sc[nt][3] = -1e30f;
            }
        }

        // ---- online softmax (exp2 domain) ----
        float mx0 = -1e30f, mx1 = -1e30f;
#pragma unroll
        for (int nt = 0; nt < 8; nt++) {
            mx0 = fmaxf(mx0, fmaxf(sc[nt][0], sc[nt][1]));
            mx1 = fmaxf(mx1, fmaxf(sc[nt][2], sc[nt][3]));
        }
        mx0 = fmaxf(mx0, __shfl_xor_sync(0xffffffffu, mx0, 1));
        mx0 = fmaxf(mx0, __shfl_xor_sync(0xffffffffu, mx0, 2));
        mx1 = fmaxf(mx1, __shfl_xor_sync(0xffffffffu, mx1, 1));
        mx1 = fmaxf(mx1, __shfl_xor_sync(0xffffffffu, mx1, 2));

        const float mn0 = fmaxf(mrow0, mx0);
        const float mn1 = fmaxf(mrow1, mx1);
        const float a0 = ex2f(mrow0 - mn0);
        const float a1 = ex2f(mrow1 - mn1);
        mrow0 = mn0; mrow1 = mn1;

#pragma unroll
        for (int nt = 0; nt < 16; nt++) {
            o[nt][0] *= a0; o[nt][1] *= a0;
            o[nt][2] *= a1; o[nt][3] *= a1;
        }

        float s0 = 0.f, s1 = 0.f;
#pragma unroll
        for (int nt = 0; nt < 8; nt++) {
            sc[nt][0] = ex2f(sc[nt][0] - mn0);
            sc[nt][1] = ex2f(sc[nt][1] - mn0);
            sc[nt][2] = ex2f(sc[nt][2] - mn1);
            sc[nt][3] = ex2f(sc[nt][3] - mn1);
            s0 += sc[nt][0] + sc[nt][1];
            s1 += sc[nt][2] + sc[nt][3];
        }
        s0 += __shfl_xor_sync(0xffffffffu, s0, 1);
        s0 += __shfl_xor_sync(0xffffffffu, s0, 2);
        s1 += __shfl_xor_sync(0xffffffffu, s1, 1);
        s1 += __shfl_xor_sync(0xffffffffu, s1, 2);
        lrow0 = lrow0 * a0 + s0;
        lrow1 = lrow1 * a1 + s1;

        // ---- O += P V (split, 3 passes; P packed from registers) ----
#pragma unroll
        for (int ks2 = 0; ks2 < 4; ks2++) {
            const int t0 = 2 * ks2, t1 = 2 * ks2 + 1;
            uint32_t ah[4], al[4];
            ah[0] = pack2(sc[t0][0], sc[t0][1]);
            ah[1] = pack2(sc[t0][2], sc[t0][3]);
            ah[2] = pack2(sc[t1][0], sc[t1][1]);
            ah[3] = pack2(sc[t1][2], sc[t1][3]);
            al[0] = pack2(sc[t0][0] - lo_f(ah[0]), sc[t0][1] - hi_f(ah[0]));
            al[1] = pack2(sc[t0][2] - lo_f(ah[1]), sc[t0][3] - hi_f(ah[1]));
            al[2] = pack2(sc[t1][0] - lo_f(ah[2]), sc[t1][1] - hi_f(ah[2]));
            al[3] = pack2(sc[t1][2] - lo_f(ah[3]), sc[t1][3] - hi_f(ah[3]));
#pragma unroll
            for (int dn = 0; dn < 8; dn++) {
                uint32_t bvh[4], bvl[4];
                const uint32_t vaddr = vhB +
                    (uint32_t)((ks2 * 16 + vrow) * FL_STR + dn * 16 + vcol) * 2;
                ldsm4t(bvh, vaddr);
                ldsm4t(bvl, vaddr + (uint32_t)FL_ARR * 2);
                mma16816(o[2 * dn + 0], ah, bvh + 0);
                mma16816(o[2 * dn + 1], ah, bvh + 2);
                mma16816(o[2 * dn + 0], al, bvh + 0);
                mma16816(o[2 * dn + 1], al, bvh + 2);
                mma16816(o[2 * dn + 0], ah, bvl + 0);
                mma16816(o[2 * dn + 1], ah, bvl + 2);
            }
        }
        __syncthreads();     // protect current slot from next iter's load
    }

    // ---- epilogue: normalize, split to bf16 hi/lo, write g_at_* ----
    const float inv0 = 1.f / lrow0;
    const float inv1 = 1.f / lrow1;
    const int r0 = qb + wq0 + (lane >> 2);
    const int r1 = r0 + 8;
#pragma unroll
    for (int nt = 0; nt < 16; nt++) {
        const int col = h * HD + nt * 8 + (lane & 3) * 2;
        {
            float v0 = o[nt][0] * inv0, v1 = o[nt][1] * inv0;
            uint32_t ph = pack2(v0, v1);
            uint32_t pl = pack2(v0 - lo_f(ph), v1 - hi_f(ph));
            *(uint32_t*)(g_at_hi + (size_t)r0 * HID + col) = ph;
            *(uint32_t*)(g_at_lo + (size_t)r0 * HID + col) = pl;
        }
        {
            float v0 = o[nt][2] * inv1, v1 = o[nt][3] * inv1;
            uint32_t ph = pack2(v0, v1);
            uint32_t pl = pack2(v0 - lo_f(ph), v1 - hi_f(ph));
            *(uint32_t*)(g_at_hi + (size_t)r1 * HID + col) = ph;
            *(uint32_t*)(g_at_lo + (size_t)r1 * HID + col) = pl;
        }
    }
}

// ---------------------------------------------------------------------------
extern "C" void kernel_launch(void* const* d_in, const int* in_sizes, int n_in,
                              void* d_out, int out_size)
{
    const float* hs   = (const float*)d_in[0];
    const float* cosp = (const float*)d_in[1];
    const float* sinp = (const float*)d_in[2];
    const float* wq   = (const float*)d_in[3];
    const float* wk   = (const float*)d_in[4];
    const float* wv   = (const float*)d_in[5];
    const float* wo   = (const float*)d_in[6];
    const float* qw   = (const float*)d_in[7];
    const float* kw   = (const float*)d_in[8];
    float* out = (float*)d_out;

    float* qkv;
    cudaGetSymbolAddress((void**)&qkv, g_qkv);

    __nv_bfloat16 *hs_hi, *hs_lo, *at_hi, *at_lo, *wqkv_hi, *wqkv_lo, *wo_hi, *wo_lo;
    cudaGetSymbolAddress((void**)&hs_hi, g_hs_hi);
    cudaGetSymbolAddress((void**)&hs_lo, g_hs_lo);
    cudaGetSymbolAddress((void**)&at_hi, g_at_hi);
    cudaGetSymbolAddress((void**)&at_lo, g_at_lo);
    cudaGetSymbolAddress((void**)&wqkv_hi, g_wqkv_hi);
    cudaGetSymbolAddress((void**)&wqkv_lo, g_wqkv_lo);
    cudaGetSymbolAddress((void**)&wo_hi, g_wo_hi);
    cudaGetSymbolAddress((void**)&wo_lo, g_wo_lo);

    cudaFuncSetAttribute(gemm_bf16x2, cudaFuncAttributeMaxDynamicSharedMemorySize,
                         (int)GEMM_SMEM);
    cudaFuncSetAttribute(flash_mma, cudaFuncAttributeMaxDynamicSharedMemorySize,
                         (int)FLASH_SMEM);

    dim3 blk(256);

    // split conversions (vectorized; sizes are /4)
    cvt_split<<<2048, blk>>>(hs, hs_hi, hs_lo, (S_LEN * HID) / 4);
    cvt_split<<<1024, blk>>>(wq, wqkv_hi,                      wqkv_lo,                      (2048 * HID) / 4);
    cvt_split<<< 512, blk>>>(wk, wqkv_hi + (size_t)2048 * HID, wqkv_lo + (size_t)2048 * HID, (1024 * HID) / 4);
    cvt_split<<< 512, blk>>>(wv, wqkv_hi + (size_t)3072 * HID, wqkv_lo + (size_t)3072 * HID, (1024 * HID) / 4);
    cvt_split<<<1024, blk>>>(wo, wo_hi, wo_lo, (HID * HID) / 4);

    // QKV projection
    gemm_bf16x2<<<dim3(QKV_W / 128, S_LEN / 128), blk, GEMM_SMEM>>>(
        hs_hi, hs_lo, wqkv_hi, wqkv_lo, qkv, HID, QKV_W);

    // norm + rope + split
    norm_rope_split<<<S_LEN, blk>>>(cosp, sinp, qw, kw);

    // flash attention (tensor cores) -> g_at_hi/lo
    flash_mma<<<dim3(S_LEN / 128, NH), blk, FLASH_SMEM>>>();

    // output projection
    gemm_bf16x2<<<dim3(HID / 128, S_LEN / 128), blk, GEMM_SMEM>>>(
        at_hi, at_lo, wo_hi, wo_lo, out, HID, HID);
}